// round 8
// baseline (speedup 1.0000x reference)
#include <cuda_runtime.h>
#include <math.h>
#include <stdint.h>

#define Bn 16
#define Qn 300
#define Dn 256
#define Hn 8
#define Pn 4
#define Fn 2048
#define HGn 100
#define WGn 100
#define HWn 10000
#define DHn 32
#define LN_EPS 1e-5f

#define BQ (Bn*Qn)            // 4800
#define MEMROWS (Bn*HWn)      // 160000

typedef unsigned long long ull;

// ---------------- scratch (allocation-free: __device__ globals) ----------------
__device__ float g_qkv[BQ*3*Dn];
__device__ float g_sa[BQ*Dn];
__device__ float g_x1[BQ*Dn];
__device__ float g_x2[BQ*Dn];
__device__ float g_x2r[BQ*Dn];
__device__ float g_tmp[BQ*Dn];
__device__ float g_ca[BQ*Dn];
__device__ float g_vals[MEMROWS*Dn];
__device__ float g_ff[BQ*Fn];
__device__ float g_wcat[Dn*128];
__device__ float g_bcat[128];
__device__ float g_lg[BQ*128];
// tf32-pre-rounded copies
__device__ float g_ipw[Dn*768];
__device__ float g_opw[Dn*Dn];
__device__ float g_vpw[Dn*Dn];
__device__ float g_oqw[Dn*Dn];
__device__ float g_l1w[Dn*Fn];
__device__ float g_l2w[Fn*Dn];
__device__ float g_tgtr[BQ*Dn];

__device__ __forceinline__ uint32_t tf32r(float x) {
    float y;
    asm("cvt.rna.tf32.f32 %0, %1;" : "=f"(y) : "f"(x));
    return __float_as_uint(y);
}
__device__ __forceinline__ float tf32f(float x) { return __uint_as_float(tf32r(x)); }

__device__ __forceinline__ ull fma2(ull a, ull b, ull c) {
    ull d;
    asm("fma.rn.f32x2 %0, %1, %2, %3;" : "=l"(d) : "l"(a), "l"(b), "l"(c));
    return d;
}

union F4U { float4 f; ull u[2]; };
union F2U { float2 f; ull u; };

// ---------------- one-shot tf32 rounding of weights + tgt ----------------
__global__ void round7_kernel(
    const float4* __restrict__ ipw, const float4* __restrict__ opw,
    const float4* __restrict__ vpw, const float4* __restrict__ oqw,
    const float4* __restrict__ l1w, const float4* __restrict__ l2w,
    const float4* __restrict__ tgt,
    float4* d_ipw, float4* d_opw, float4* d_vpw, float4* d_oqw,
    float4* d_l1w, float4* d_l2w, float4* d_tgt)
{
    int bi = blockIdx.x;
    const float4* s; float4* d; int base;
    if      (bi <  192) { s = ipw; d = d_ipw; base = bi; }
    else if (bi <  256) { s = opw; d = d_opw; base = bi - 192; }
    else if (bi <  320) { s = vpw; d = d_vpw; base = bi - 256; }
    else if (bi <  384) { s = oqw; d = d_oqw; base = bi - 320; }
    else if (bi <  896) { s = l1w; d = d_l1w; base = bi - 384; }
    else if (bi < 1408) { s = l2w; d = d_l2w; base = bi - 896; }
    else                { s = tgt; d = d_tgt; base = bi - 1408; }
    int idx = base * 256 + threadIdx.x;
    float4 v = s[idx];
    v.x = tf32f(v.x); v.y = tf32f(v.y); v.z = tf32f(v.z); v.w = tf32f(v.w);
    d[idx] = v;
}

// ---------------- common GEMM constants ----------------
#define TBN 128
#define TBK 16
#define APITCH (TBK + 4)    // 20
#define BPITCH (TBN + 8)    // 136

__device__ __forceinline__ void cp16(void* dst, const void* src) {
    uint32_t d = (uint32_t)__cvta_generic_to_shared(dst);
    asm volatile("cp.async.ca.shared.global [%0], [%1], 16;" :: "r"(d), "l"(src));
}

#define MMA_TF32(c, a, b) \
    asm volatile( \
        "mma.sync.aligned.m16n8k8.row.col.f32.tf32.tf32.f32 " \
        "{%0,%1,%2,%3}, {%4,%5,%6,%7}, {%8,%9}, {%0,%1,%2,%3};" \
        : "+f"((c)[0]), "+f"((c)[1]), "+f"((c)[2]), "+f"((c)[3]) \
        : "r"((a)[0]), "r"((a)[1]), "r"((a)[2]), "r"((a)[3]), \
          "r"((b)[0]), "r"((b)[1]))

// ---------------- generic 64x128 tf32 GEMM (pre-rounded A and B) ----------------
__global__ __launch_bounds__(256) void gemm_tf32_async(
    const float* __restrict__ A, const float* __restrict__ W,
    const float* __restrict__ bias, float* __restrict__ C,
    int M, int N, int K, int relu, int rndout)
{
    extern __shared__ float smem[];
    float (*As)[64][APITCH] = (float(*)[64][APITCH])smem;
    float (*Bs)[TBK][BPITCH] = (float(*)[TBK][BPITCH])(smem + 3 * 64 * APITCH);

    const int tid  = threadIdx.x;
    const int lane = tid & 31;
    const int warp = tid >> 5;
    const int wm = (warp >> 2) * 32;
    const int wn = (warp & 3) * 32;
    const int bm = blockIdx.y * 64;
    const int bn = blockIdx.x * TBN;

    const int lq = lane >> 2;
    const int lr = lane & 3;

    const int a_row = tid >> 2;
    const int a_col = (tid & 3) * 4;
    const int b_row = tid >> 4;
    const int b_col = (tid & 15) * 8;

    const float* Aptr = A + (size_t)(bm + a_row) * K + a_col;
    const float* Wptr = W + (size_t)b_row * N + bn + b_col;

    float c[2][4][4];
#pragma unroll
    for (int i = 0; i < 2; i++)
#pragma unroll
        for (int j = 0; j < 4; j++)
#pragma unroll
            for (int l = 0; l < 4; l++) c[i][j][l] = 0.f;

    const int nk = K / TBK;

#pragma unroll
    for (int s = 0; s < 2; s++) {
        int kt = s * TBK;
        cp16(&As[s][a_row][a_col], Aptr + kt);
        cp16(&Bs[s][b_row][b_col],     Wptr + (size_t)kt * N);
        cp16(&Bs[s][b_row][b_col + 4], Wptr + (size_t)kt * N + 4);
        asm volatile("cp.async.commit_group;" ::: "memory");
    }

    for (int it = 0; it < nk; it++) {
        asm volatile("cp.async.wait_group 1;" ::: "memory");
        __syncthreads();

        int nxt = it + 2;
        if (nxt < nk) {
            int s = nxt % 3;
            int kt = nxt * TBK;
            cp16(&As[s][a_row][a_col], Aptr + kt);
            cp16(&Bs[s][b_row][b_col],     Wptr + (size_t)kt * N);
            cp16(&Bs[s][b_row][b_col + 4], Wptr + (size_t)kt * N + 4);
        }
        asm volatile("cp.async.commit_group;" ::: "memory");

        const int buf = it % 3;
#pragma unroll
        for (int ks = 0; ks < TBK; ks += 8) {
            uint32_t a[2][4], b[4][2];
#pragma unroll
            for (int mt = 0; mt < 2; mt++) {
                int mr = wm + mt * 16 + lq;
                a[mt][0] = __float_as_uint(As[buf][mr    ][ks + lr]);
                a[mt][1] = __float_as_uint(As[buf][mr + 8][ks + lr]);
                a[mt][2] = __float_as_uint(As[buf][mr    ][ks + lr + 4]);
                a[mt][3] = __float_as_uint(As[buf][mr + 8][ks + lr + 4]);
            }
#pragma unroll
            for (int nt = 0; nt < 4; nt++) {
                int nc = wn + nt * 8 + lq;
                b[nt][0] = __float_as_uint(Bs[buf][ks + lr    ][nc]);
                b[nt][1] = __float_as_uint(Bs[buf][ks + lr + 4][nc]);
            }
#pragma unroll
            for (int mt = 0; mt < 2; mt++)
#pragma unroll
                for (int nt = 0; nt < 4; nt++)
                    MMA_TF32(c[mt][nt], a[mt], b[nt]);
        }
    }

#pragma unroll
    for (int mt = 0; mt < 2; mt++) {
#pragma unroll
        for (int nt = 0; nt < 4; nt++) {
            int row = bm + wm + mt * 16 + lq;
            int col = bn + wn + nt * 8 + lr * 2;
            float b0 = bias[col], b1 = bias[col + 1];
            float v0 = c[mt][nt][0] + b0;
            float v1 = c[mt][nt][1] + b1;
            float v2 = c[mt][nt][2] + b0;
            float v3 = c[mt][nt][3] + b1;
            if (relu) {
                v0 = fmaxf(v0, 0.f); v1 = fmaxf(v1, 0.f);
                v2 = fmaxf(v2, 0.f); v3 = fmaxf(v3, 0.f);
            }
            if (rndout) {
                v0 = tf32f(v0); v1 = tf32f(v1); v2 = tf32f(v2); v3 = tf32f(v3);
            }
            *(float2*)&C[(size_t)row * N + col]       = make_float2(v0, v1);
            *(float2*)&C[(size_t)(row + 8) * N + col] = make_float2(v2, v3);
        }
    }
}

// ---------------- vproj GEMM: 128x128 block, 4 warps, 64x64 warp tiles ----------------
// A raw fp32 (rna cvt at fragment load), W pre-rounded. K=256, N=256 multiples.
__global__ __launch_bounds__(128) void gemm_vproj(
    const float* __restrict__ A, const float* __restrict__ W,
    const float* __restrict__ bias, float* __restrict__ C,
    int M, int N, int K)
{
    extern __shared__ float smem[];
    float (*As)[128][APITCH] = (float(*)[128][APITCH])smem;
    float (*Bs)[TBK][BPITCH] = (float(*)[TBK][BPITCH])(smem + 3 * 128 * APITCH);

    const int tid  = threadIdx.x;   // 0..127
    const int lane = tid & 31;
    const int warp = tid >> 5;      // 0..3
    const int wm = (warp >> 1) * 64;
    const int wn = (warp & 1) * 64;
    const int bm = blockIdx.y * 128;
    const int bn = blockIdx.x * 128;

    const int lq = lane >> 2;
    const int lr = lane & 3;

    // A staging: 128 rows x 16 floats = 512 cp16; 4 per thread
    const int a_row = tid >> 2;          // 0..31 (+32*i)
    const int a_col = (tid & 3) * 4;
    // B staging: 16 rows x 128 floats = 512 cp16; 4 per thread
    const int b_row = tid >> 3;          // 0..15
    const int b_col = (tid & 7) * 16;

    const float* Aptr = A + (size_t)(bm + a_row) * K + a_col;
    const float* Wptr = W + (size_t)b_row * N + bn + b_col;

    float c[4][8][4];
#pragma unroll
    for (int i = 0; i < 4; i++)
#pragma unroll
        for (int j = 0; j < 8; j++)
#pragma unroll
            for (int l = 0; l < 4; l++) c[i][j][l] = 0.f;

    const int nk = K / TBK;

#pragma unroll
    for (int s = 0; s < 2; s++) {
        int kt = s * TBK;
#pragma unroll
        for (int i = 0; i < 4; i++)
            cp16(&As[s][a_row + 32 * i][a_col], Aptr + (size_t)(32 * i) * K + kt);
        const float* wp = Wptr + (size_t)kt * N;
        cp16(&Bs[s][b_row][b_col],      wp);
        cp16(&Bs[s][b_row][b_col + 4],  wp + 4);
        cp16(&Bs[s][b_row][b_col + 8],  wp + 8);
        cp16(&Bs[s][b_row][b_col + 12], wp + 12);
        asm volatile("cp.async.commit_group;" ::: "memory");
    }

    for (int it = 0; it < nk; it++) {
        asm volatile("cp.async.wait_group 1;" ::: "memory");
        __syncthreads();

        int nxt = it + 2;
        if (nxt < nk) {
            int s = nxt % 3;
            int kt = nxt * TBK;
#pragma unroll
            for (int i = 0; i < 4; i++)
                cp16(&As[s][a_row + 32 * i][a_col], Aptr + (size_t)(32 * i) * K + kt);
            const float* wp = Wptr + (size_t)kt * N;
            cp16(&Bs[s][b_row][b_col],      wp);
            cp16(&Bs[s][b_row][b_col + 4],  wp + 4);
            cp16(&Bs[s][b_row][b_col + 8],  wp + 8);
            cp16(&Bs[s][b_row][b_col + 12], wp + 12);
        }
        asm volatile("cp.async.commit_group;" ::: "memory");

        const int buf = it % 3;
#pragma unroll
        for (int ks = 0; ks < TBK; ks += 8) {
            uint32_t a[4][4], b[8][2];
#pragma unroll
            for (int mt = 0; mt < 4; mt++) {
                int mr = wm + mt * 16 + lq;
                a[mt][0] = tf32r(As[buf][mr    ][ks + lr]);
                a[mt][1] = tf32r(As[buf][mr + 8][ks + lr]);
                a[mt][2] = tf32r(As[buf][mr    ][ks + lr + 4]);
                a[mt][3] = tf32r(As[buf][mr + 8][ks + lr + 4]);
            }
#pragma unroll
            for (int nt = 0; nt < 8; nt++) {
                int nc = wn + nt * 8 + lq;
                b[nt][0] = __float_as_uint(Bs[buf][ks + lr    ][nc]);
                b[nt][1] = __float_as_uint(Bs[buf][ks + lr + 4][nc]);
            }
#pragma unroll
            for (int mt = 0; mt < 4; mt++)
#pragma unroll
                for (int nt = 0; nt < 8; nt++)
                    MMA_TF32(c[mt][nt], a[mt], b[nt]);
        }
    }

#pragma unroll
    for (int mt = 0; mt < 4; mt++) {
#pragma unroll
        for (int nt = 0; nt < 8; nt++) {
            int row = bm + wm + mt * 16 + lq;
            int col = bn + wn + nt * 8 + lr * 2;
            float b0 = bias[col], b1 = bias[col + 1];
            *(float2*)&C[(size_t)row * N + col]       = make_float2(c[mt][nt][0] + b0, c[mt][nt][1] + b1);
            *(float2*)&C[(size_t)(row + 8) * N + col] = make_float2(c[mt][nt][2] + b0, c[mt][nt][3] + b1);
        }
    }
}

// ---------------- fp32 FFMA tiled SGEMM (accuracy-critical logits) ----------------
#define BM 64
#define BNf 64
#define BKf 16

__global__ __launch_bounds__(256) void gemm_f32_kernel(
    const float* __restrict__ A, const float* __restrict__ W,
    const float* __restrict__ bias, float* __restrict__ C,
    int M, int N, int K)
{
    __shared__ float As[BKf][BM];
    __shared__ float Bs[BKf][BNf];
    int tid = threadIdx.x;
    int tx = tid & 15, ty = tid >> 4;
    int bm = blockIdx.y * BM, bn = blockIdx.x * BNf;

    float acc[4][4];
#pragma unroll
    for (int i = 0; i < 4; i++)
#pragma unroll
        for (int j = 0; j < 4; j++) acc[i][j] = 0.f;

    int a_row = tid >> 2;
    int a_col = (tid & 3) * 4;
    int b_row = tid >> 4;
    int b_col = (tid & 15) * 4;

    const float* Aptr = A + (size_t)(bm + a_row) * K + a_col;
    const float* Wptr = W + (size_t)b_row * N + bn + b_col;

    for (int kt = 0; kt < K; kt += BKf) {
        float4 av = *(const float4*)(Aptr + kt);
        As[a_col + 0][a_row] = av.x;
        As[a_col + 1][a_row] = av.y;
        As[a_col + 2][a_row] = av.z;
        As[a_col + 3][a_row] = av.w;
        float4 bv = *(const float4*)(Wptr + (size_t)kt * N);
        *(float4*)&Bs[b_row][b_col] = bv;
        __syncthreads();
#pragma unroll
        for (int kk = 0; kk < BKf; kk++) {
            float ar[4], br[4];
#pragma unroll
            for (int i = 0; i < 4; i++) ar[i] = As[kk][ty + 16 * i];
#pragma unroll
            for (int j = 0; j < 4; j++) br[j] = Bs[kk][tx + 16 * j];
#pragma unroll
            for (int i = 0; i < 4; i++)
#pragma unroll
                for (int j = 0; j < 4; j++) acc[i][j] += ar[i] * br[j];
        }
        __syncthreads();
    }

#pragma unroll
    for (int i = 0; i < 4; i++) {
        int row = bm + ty + 16 * i;
#pragma unroll
        for (int j = 0; j < 4; j++) {
            int col = bn + tx + 16 * j;
            C[(size_t)row * N + col] = acc[i][j] + bias[col];
        }
    }
}

// ---------------- concat ref/off/attw weights into padded [256,128] ----------------
__global__ void concat_w_kernel(
    const float* __restrict__ ref_w, const float* __restrict__ ref_b,
    const float* __restrict__ off_w, const float* __restrict__ off_b,
    const float* __restrict__ attw_w, const float* __restrict__ attw_b,
    float* __restrict__ Wc, float* __restrict__ bc)
{
    int i = blockIdx.x * 256 + threadIdx.x;
    if (i < Dn * 128) {
        int d = i >> 7, j = i & 127;
        float v = 0.f;
        if (j < 2) v = ref_w[d * 2 + j];
        else if (j < 66) v = off_w[d * 64 + (j - 2)];
        else if (j < 98) v = attw_w[d * 32 + (j - 66)];
        Wc[i] = v;
    }
    if (i < 128) {
        float v = 0.f;
        if (i < 2) v = ref_b[i];
        else if (i < 66) v = off_b[i - 2];
        else if (i < 98) v = attw_b[i - 66];
        bc[i] = v;
    }
}

// ---------------- flash self-attention: no-max softmax + packed f32x2 ----------------
#define KT 60

__global__ __launch_bounds__(128) void flash_kernel(
    const float* __restrict__ qkv, float* __restrict__ sa)
{
    __shared__ float4 Ks[KT][8];
    __shared__ float4 Vs[KT][8];

    const int bh = blockIdx.y;
    const int b = bh >> 3, h = bh & 7;
    const int qi = blockIdx.x * 128 + threadIdx.x;
    const bool act = qi < Qn;
    const int tid = threadIdx.x;

    ull q2[16], acc2[16];
    const float* qp = qkv + (size_t)(b * Qn + (act ? qi : 0)) * (3 * Dn) + h * DHn;
#pragma unroll
    for (int i = 0; i < 8; i++) {
        F4U t; t.f = *(const float4*)(qp + i * 4);
        q2[2 * i] = t.u[0]; q2[2 * i + 1] = t.u[1];
    }
#pragma unroll
    for (int i = 0; i < 16; i++) acc2[i] = 0ull;

    float su = 0.f;
    const float scale = 0.17677669529663689f;

    const float* kbase = qkv + (size_t)(b * Qn) * (3 * Dn) + Dn + h * DHn;
    const float* vbase = kbase + Dn;

    for (int t0 = 0; t0 < Qn; t0 += KT) {
        for (int i = tid; i < KT * 8; i += 128) {
            int j = i >> 3, dc = i & 7;
            size_t off = (size_t)(t0 + j) * (3 * Dn) + dc * 4;
            Ks[j][dc] = *(const float4*)(kbase + off);
            Vs[j][dc] = *(const float4*)(vbase + off);
        }
        __syncthreads();

#pragma unroll 2
        for (int j = 0; j < KT; j++) {
            ull s2a = 0ull, s2b = 0ull;
#pragma unroll
            for (int i = 0; i < 4; i++) {
                F4U ka; ka.f = Ks[j][2 * i];
                F4U kb; kb.f = Ks[j][2 * i + 1];
                s2a = fma2(q2[4 * i    ], ka.u[0], s2a);
                s2b = fma2(q2[4 * i + 1], ka.u[1], s2b);
                s2a = fma2(q2[4 * i + 2], kb.u[0], s2a);
                s2b = fma2(q2[4 * i + 3], kb.u[1], s2b);
            }
            F2U ua; ua.u = s2a;
            F2U ub; ub.u = s2b;
            float s = (ua.f.x + ua.f.y + ub.f.x + ub.f.y) * scale;
            float p = __expf(s);
            su += p;
            F2U pp; pp.f = make_float2(p, p);
            ull p2 = pp.u;
#pragma unroll
            for (int i = 0; i < 4; i++) {
                F4U va; va.f = Vs[j][2 * i];
                F4U vb; vb.f = Vs[j][2 * i + 1];
                acc2[4 * i    ] = fma2(p2, va.u[0], acc2[4 * i    ]);
                acc2[4 * i + 1] = fma2(p2, va.u[1], acc2[4 * i + 1]);
                acc2[4 * i + 2] = fma2(p2, vb.u[0], acc2[4 * i + 2]);
                acc2[4 * i + 3] = fma2(p2, vb.u[1], acc2[4 * i + 3]);
            }
        }
        __syncthreads();
    }

    if (act) {
        float inv = 1.f / su;
        float* op = sa + (size_t)(b * Qn + qi) * Dn + h * DHn;
#pragma unroll
        for (int i = 0; i < 8; i++) {
            F2U lo; lo.u = acc2[2 * i];
            F2U hi; hi.u = acc2[2 * i + 1];
            float4 v = make_float4(tf32f(lo.f.x * inv), tf32f(lo.f.y * inv),
                                   tf32f(hi.f.x * inv), tf32f(hi.f.y * inv));
            *(float4*)(op + i * 4) = v;
        }
    }
}

// ---------------- fused residual-add + LayerNorm ----------------
__global__ void add_ln_kernel(const float* __restrict__ a, const float* __restrict__ r,
                              const float* __restrict__ g, const float* __restrict__ be,
                              float* __restrict__ out, float* __restrict__ out_r)
{
    int row = blockIdx.x, t = threadIdx.x;
    size_t idx = (size_t)row * Dn + t;
    float v = a[idx] + r[idx];
    __shared__ float red[8];
    float s = v;
#pragma unroll
    for (int o = 16; o; o >>= 1) s += __shfl_xor_sync(~0u, s, o);
    if ((t & 31) == 0) red[t >> 5] = s;
    __syncthreads();
    float mean = 0.f;
#pragma unroll
    for (int i = 0; i < 8; i++) mean += red[i];
    mean *= (1.f / Dn);
    float d = v - mean;
    float s2 = d * d;
#pragma unroll
    for (int o = 16; o; o >>= 1) s2 += __shfl_xor_sync(~0u, s2, o);
    __syncthreads();
    if ((t & 31) == 0) red[t >> 5] = s2;
    __syncthreads();
    float var = 0.f;
#pragma unroll
    for (int i = 0; i < 8; i++) var += red[i];
    var *= (1.f / Dn);
    float o2 = d * rsqrtf(var + LN_EPS) * g[t] + be[t];
    out[idx] = o2;
    if (out_r) out_r[idx] = tf32f(o2);
}

// ---------------- sampler: sigmoid/softmax + bilinear gather ----------------
__global__ __launch_bounds__(256) void sampler_kernel(
    const float* __restrict__ lgbuf, const float* __restrict__ vals,
    float* __restrict__ ca)
{
    __shared__ float lg[128];
    __shared__ float sref[2];
    __shared__ float swts[Hn * Pn];

    int bq = blockIdx.x;
    int b = bq / Qn;
    int t = threadIdx.x;

    if (t < 128) lg[t] = lgbuf[(size_t)bq * 128 + t];
    __syncthreads();

    if (t < 2) sref[t] = 1.f / (1.f + expf(-lg[t]));
    else if (t >= 32 && t < 40) {
        int h = t - 32;
        const float* al = &lg[66 + h * 4];
        float m = fmaxf(fmaxf(al[0], al[1]), fmaxf(al[2], al[3]));
        float e0 = expf(al[0]-m), e1 = expf(al[1]-m), e2 = expf(al[2]-m), e3 = expf(al[3]-m);
        float inv = 1.f / (e0 + e1 + e2 + e3);
        swts[h*4+0] = e0*inv; swts[h*4+1] = e1*inv; swts[h*4+2] = e2*inv; swts[h*4+3] = e3*inv;
    }
    __syncthreads();

    int h = t >> 5, d = t & 31;
    float rx = sref[0], ry = sref[1];
    const float* vb = vals + (size_t)b * HWn * Dn + h * DHn + d;
    float acc = 0.f;
#pragma unroll
    for (int p = 0; p < Pn; p++) {
        float lx = fminf(fmaxf(rx + lg[2 + h * 8 + p * 2 + 0], 0.f), 1.f);
        float ly = fminf(fmaxf(ry + lg[2 + h * 8 + p * 2 + 1], 0.f), 1.f);
        float sx = lx * (float)(WGn - 1);
        float sy = ly * (float)(HGn - 1);
        float x0f = floorf(sx), y0f = floorf(sy);
        int x0 = min(max((int)x0f, 0), WGn - 1);
        int y0 = min(max((int)y0f, 0), HGn - 1);
        int x1i = min(x0 + 1, WGn - 1);
        int y1i = min(y0 + 1, HGn - 1);
        float wx1 = sx - x0f, wx0 = 1.f - wx1;
        float wy1 = sy - y0f, wy0 = 1.f - wy1;
        float v00 = vb[(size_t)(y0  * WGn + x0 ) * Dn];
        float v01 = vb[(size_t)(y1i * WGn + x0 ) * Dn];
        float v10 = vb[(size_t)(y0  * WGn + x1i) * Dn];
        float v11 = vb[(size_t)(y1i * WGn + x1i) * Dn];
        float bil = v00 * wx0 * wy0 + v01 * wx0 * wy1 + v10 * wx1 * wy0 + v11 * wx1 * wy1;
        acc += swts[h * 4 + p] * bil;
    }
    ca[(size_t)bq * Dn + t] = tf32f(acc);
}

// ---------------- launch ----------------
extern "C" void kernel_launch(void* const* d_in, const int* in_sizes, int n_in,
                              void* d_out, int out_size)
{
    const float* tgt        = (const float*)d_in[0];
    const float* memory     = (const float*)d_in[1];
    const float* in_proj_w  = (const float*)d_in[2];
    const float* in_proj_b  = (const float*)d_in[3];
    const float* out_proj_w = (const float*)d_in[4];
    const float* out_proj_b = (const float*)d_in[5];
    const float* norm1_g    = (const float*)d_in[6];
    const float* norm1_b    = (const float*)d_in[7];
    const float* ref_w      = (const float*)d_in[8];
    const float* ref_b      = (const float*)d_in[9];
    const float* off_w      = (const float*)d_in[10];
    const float* off_b      = (const float*)d_in[11];
    const float* attw_w     = (const float*)d_in[12];
    const float* attw_b     = (const float*)d_in[13];
    const float* vproj_w    = (const float*)d_in[14];
    const float* vproj_b    = (const float*)d_in[15];
    const float* oproj_w    = (const float*)d_in[16];
    const float* oproj_b    = (const float*)d_in[17];
    const float* norm2_g    = (const float*)d_in[18];
    const float* norm2_b    = (const float*)d_in[19];
    const float* lin1_w     = (const float*)d_in[20];
    const float* lin1_b     = (const float*)d_in[21];
    const float* lin2_w     = (const float*)d_in[22];
    const float* lin2_b     = (const float*)d_in[23];
    const float* norm3_g    = (const float*)d_in[24];
    const float* norm3_b    = (const float*)d_in[25];
    float* out = (float*)d_out;

    float *qkv, *sa, *x1, *x2, *x2r, *tmp, *ca, *vals, *ff, *wcat, *bcat, *lgb;
    float *ipw, *opw, *vpw, *oqw, *l1w, *l2w, *tgtr;
    cudaGetSymbolAddress((void**)&qkv,  g_qkv);
    cudaGetSymbolAddress((void**)&sa,   g_sa);
    cudaGetSymbolAddress((void**)&x1,   g_x1);
    cudaGetSymbolAddress((void**)&x2,   g_x2);
    cudaGetSymbolAddress((void**)&x2r,  g_x2r);
    cudaGetSymbolAddress((void**)&tmp,  g_tmp);
    cudaGetSymbolAddress((void**)&ca,   g_ca);
    cudaGetSymbolAddress((void**)&vals, g_vals);
    cudaGetSymbolAddress((void**)&ff,   g_ff);
    cudaGetSymbolAddress((void**)&wcat, g_wcat);
    cudaGetSymbolAddress((void**)&bcat, g_bcat);
    cudaGetSymbolAddress((void**)&lgb,  g_lg);
    cudaGetSymbolAddress((void**)&ipw,  g_ipw);
    cudaGetSymbolAddress((void**)&opw,  g_opw);
    cudaGetSymbolAddress((void**)&vpw,  g_vpw);
    cudaGetSymbolAddress((void**)&oqw,  g_oqw);
    cudaGetSymbolAddress((void**)&l1w,  g_l1w);
    cudaGetSymbolAddress((void**)&l2w,  g_l2w);
    cudaGetSymbolAddress((void**)&tgtr, g_tgtr);

    const int smem1 = (3 * 64  * APITCH + 3 * TBK * BPITCH) * 4;  // 41472
    const int smem2 = (3 * 128 * APITCH + 3 * TBK * BPITCH) * 4;  // 56832
    cudaFuncSetAttribute((const void*)gemm_tf32_async, cudaFuncAttributeMaxDynamicSharedMemorySize, smem1);
    cudaFuncSetAttribute((const void*)gemm_vproj,      cudaFuncAttributeMaxDynamicSharedMemorySize, smem2);

    // 0. pre-round weights + tgt; concat logits weights (fp32)
    round7_kernel<<<2608, 256>>>(
        (const float4*)in_proj_w, (const float4*)out_proj_w, (const float4*)vproj_w,
        (const float4*)oproj_w, (const float4*)lin1_w, (const float4*)lin2_w,
        (const float4*)tgt,
        (float4*)ipw, (float4*)opw, (float4*)vpw, (float4*)oqw,
        (float4*)l1w, (float4*)l2w, (float4*)tgtr);
    concat_w_kernel<<<128, 256>>>(ref_w, ref_b, off_w, off_b, attw_w, attw_b, wcat, bcat);
    // 1. qkv projection [4800,256]@[256,768]
    gemm_tf32_async<<<dim3(768 / TBN, BQ / 64), 256, smem1>>>(tgtr, ipw, in_proj_b, qkv, BQ, 768, Dn, 0, 0);
    // 2. value projection of memory [160000,256]@[256,256] — fat warp tiles
    gemm_vproj<<<dim3(Dn / 128, MEMROWS / 128), 128, smem2>>>(memory, vpw, vproj_b, vals, MEMROWS, Dn, Dn);
    // 3. fused self-attention
    flash_kernel<<<dim3((Qn + 127) / 128, Bn * Hn), 128>>>(qkv, sa);
    // 4. out_proj
    gemm_tf32_async<<<dim3(Dn / TBN, BQ / 64), 256, smem1>>>(sa, opw, out_proj_b, tmp, BQ, Dn, Dn, 0, 0);
    // 5. x1 = LN(tgt + sa_out)
    add_ln_kernel<<<BQ, Dn>>>(tgt, tmp, norm1_g, norm1_b, x1, nullptr);
    // 6. logits — fp32 (accuracy-critical)
    gemm_f32_kernel<<<dim3(128 / BNf, BQ / BM), 256>>>(x1, wcat, bcat, lgb, BQ, 128, Dn);
    // 7. sampler -> ca (tf32-rounded)
    sampler_kernel<<<BQ, 256>>>(lgb, vals, ca);
    // 8. oproj
    gemm_tf32_async<<<dim3(Dn / TBN, BQ / 64), 256, smem1>>>(ca, oqw, oproj_b, tmp, BQ, Dn, Dn, 0, 0);
    // 9. x2 = LN(x1 + ca_out); x2r = tf32(x2)
    add_ln_kernel<<<BQ, Dn>>>(x1, tmp, norm2_g, norm2_b, x2, x2r);
    // 10. FFN lin1 + ReLU (tf32-rounded out)
    gemm_tf32_async<<<dim3(Fn / TBN, BQ / 64), 256, smem1>>>(x2r, l1w, lin1_b, ff, BQ, Fn, Dn, 1, 1);
    // 11. FFN lin2
    gemm_tf32_async<<<dim3(Dn / TBN, BQ / 64), 256, smem1>>>(ff, l2w, lin2_b, tmp, BQ, Dn, Fn, 0, 0);
    // 12. out = LN(x2 + ffn)
    add_ln_kernel<<<BQ, Dn>>>(x2, tmp, norm3_g, norm3_b, out, nullptr);
}

// round 9
// speedup vs baseline: 1.3423x; 1.3423x over previous
#include <cuda_runtime.h>
#include <math.h>
#include <stdint.h>

#define Bn 16
#define Qn 300
#define Dn 256
#define Hn 8
#define Pn 4
#define Fn 2048
#define HGn 100
#define WGn 100
#define HWn 10000
#define DHn 32
#define LN_EPS 1e-5f

#define BQ (Bn*Qn)            // 4800
#define MEMROWS (Bn*HWn)      // 160000

typedef unsigned long long ull;

// ---------------- scratch (allocation-free: __device__ globals) ----------------
__device__ float g_qkv[BQ*3*Dn];
__device__ float g_sa[BQ*Dn];
__device__ float g_x1[BQ*Dn];
__device__ float g_x2[BQ*Dn];
__device__ float g_x2r[BQ*Dn];
__device__ float g_tmp[BQ*Dn];
__device__ float g_ca[BQ*Dn];
__device__ float g_me[Hn*BQ*Dn];      // per-head effective memory vectors [h][bq][d]
__device__ float g_ff[BQ*Fn];
__device__ float g_wcat[Dn*128];
__device__ float g_bcat[128];
__device__ float g_lg[BQ*128];
// tf32-pre-rounded copies
__device__ float g_ipw[Dn*768];
__device__ float g_opw[Dn*Dn];
__device__ float g_vpw[Dn*Dn];
__device__ float g_oqw[Dn*Dn];
__device__ float g_l1w[Dn*Fn];
__device__ float g_l2w[Fn*Dn];
__device__ float g_tgtr[BQ*Dn];

__device__ __forceinline__ uint32_t tf32r(float x) {
    float y;
    asm("cvt.rna.tf32.f32 %0, %1;" : "=f"(y) : "f"(x));
    return __float_as_uint(y);
}
__device__ __forceinline__ float tf32f(float x) { return __uint_as_float(tf32r(x)); }

__device__ __forceinline__ ull fma2(ull a, ull b, ull c) {
    ull d;
    asm("fma.rn.f32x2 %0, %1, %2, %3;" : "=l"(d) : "l"(a), "l"(b), "l"(c));
    return d;
}

union F4U { float4 f; ull u[2]; };
union F2U { float2 f; ull u; };

// ---------------- one-shot tf32 rounding of weights + tgt ----------------
__global__ void round7_kernel(
    const float4* __restrict__ ipw, const float4* __restrict__ opw,
    const float4* __restrict__ vpw, const float4* __restrict__ oqw,
    const float4* __restrict__ l1w, const float4* __restrict__ l2w,
    const float4* __restrict__ tgt,
    float4* d_ipw, float4* d_opw, float4* d_vpw, float4* d_oqw,
    float4* d_l1w, float4* d_l2w, float4* d_tgt)
{
    int bi = blockIdx.x;
    const float4* s; float4* d; int base;
    if      (bi <  192) { s = ipw; d = d_ipw; base = bi; }
    else if (bi <  256) { s = opw; d = d_opw; base = bi - 192; }
    else if (bi <  320) { s = vpw; d = d_vpw; base = bi - 256; }
    else if (bi <  384) { s = oqw; d = d_oqw; base = bi - 320; }
    else if (bi <  896) { s = l1w; d = d_l1w; base = bi - 384; }
    else if (bi < 1408) { s = l2w; d = d_l2w; base = bi - 896; }
    else                { s = tgt; d = d_tgt; base = bi - 1408; }
    int idx = base * 256 + threadIdx.x;
    float4 v = s[idx];
    v.x = tf32f(v.x); v.y = tf32f(v.y); v.z = tf32f(v.z); v.w = tf32f(v.w);
    d[idx] = v;
}

// ---------------- common GEMM constants ----------------
#define TBN 128
#define TBK 16
#define APITCH (TBK + 4)    // 20
#define BPITCH (TBN + 8)    // 136

__device__ __forceinline__ void cp16(void* dst, const void* src) {
    uint32_t d = (uint32_t)__cvta_generic_to_shared(dst);
    asm volatile("cp.async.ca.shared.global [%0], [%1], 16;" :: "r"(d), "l"(src));
}

#define MMA_TF32(c, a, b) \
    asm volatile( \
        "mma.sync.aligned.m16n8k8.row.col.f32.tf32.tf32.f32 " \
        "{%0,%1,%2,%3}, {%4,%5,%6,%7}, {%8,%9}, {%0,%1,%2,%3};" \
        : "+f"((c)[0]), "+f"((c)[1]), "+f"((c)[2]), "+f"((c)[3]) \
        : "r"((a)[0]), "r"((a)[1]), "r"((a)[2]), "r"((a)[3]), \
          "r"((b)[0]), "r"((b)[1]))

// ---------------- generic 64x128 tf32 GEMM (pre-rounded A and B) ----------------
__global__ __launch_bounds__(256) void gemm_tf32_async(
    const float* __restrict__ A, const float* __restrict__ W,
    const float* __restrict__ bias, float* __restrict__ C,
    int M, int N, int K, int relu, int rndout)
{
    extern __shared__ float smem[];
    float (*As)[64][APITCH] = (float(*)[64][APITCH])smem;
    float (*Bs)[TBK][BPITCH] = (float(*)[TBK][BPITCH])(smem + 3 * 64 * APITCH);

    const int tid  = threadIdx.x;
    const int lane = tid & 31;
    const int warp = tid >> 5;
    const int wm = (warp >> 2) * 32;
    const int wn = (warp & 3) * 32;
    const int bm = blockIdx.y * 64;
    const int bn = blockIdx.x * TBN;

    const int lq = lane >> 2;
    const int lr = lane & 3;

    const int a_row = tid >> 2;
    const int a_col = (tid & 3) * 4;
    const int b_row = tid >> 4;
    const int b_col = (tid & 15) * 8;

    const float* Aptr = A + (size_t)(bm + a_row) * K + a_col;
    const float* Wptr = W + (size_t)b_row * N + bn + b_col;

    float c[2][4][4];
#pragma unroll
    for (int i = 0; i < 2; i++)
#pragma unroll
        for (int j = 0; j < 4; j++)
#pragma unroll
            for (int l = 0; l < 4; l++) c[i][j][l] = 0.f;

    const int nk = K / TBK;

#pragma unroll
    for (int s = 0; s < 2; s++) {
        int kt = s * TBK;
        cp16(&As[s][a_row][a_col], Aptr + kt);
        cp16(&Bs[s][b_row][b_col],     Wptr + (size_t)kt * N);
        cp16(&Bs[s][b_row][b_col + 4], Wptr + (size_t)kt * N + 4);
        asm volatile("cp.async.commit_group;" ::: "memory");
    }

    for (int it = 0; it < nk; it++) {
        asm volatile("cp.async.wait_group 1;" ::: "memory");
        __syncthreads();

        int nxt = it + 2;
        if (nxt < nk) {
            int s = nxt % 3;
            int kt = nxt * TBK;
            cp16(&As[s][a_row][a_col], Aptr + kt);
            cp16(&Bs[s][b_row][b_col],     Wptr + (size_t)kt * N);
            cp16(&Bs[s][b_row][b_col + 4], Wptr + (size_t)kt * N + 4);
        }
        asm volatile("cp.async.commit_group;" ::: "memory");

        const int buf = it % 3;
#pragma unroll
        for (int ks = 0; ks < TBK; ks += 8) {
            uint32_t a[2][4], b[4][2];
#pragma unroll
            for (int mt = 0; mt < 2; mt++) {
                int mr = wm + mt * 16 + lq;
                a[mt][0] = __float_as_uint(As[buf][mr    ][ks + lr]);
                a[mt][1] = __float_as_uint(As[buf][mr + 8][ks + lr]);
                a[mt][2] = __float_as_uint(As[buf][mr    ][ks + lr + 4]);
                a[mt][3] = __float_as_uint(As[buf][mr + 8][ks + lr + 4]);
            }
#pragma unroll
            for (int nt = 0; nt < 4; nt++) {
                int nc = wn + nt * 8 + lq;
                b[nt][0] = __float_as_uint(Bs[buf][ks + lr    ][nc]);
                b[nt][1] = __float_as_uint(Bs[buf][ks + lr + 4][nc]);
            }
#pragma unroll
            for (int mt = 0; mt < 2; mt++)
#pragma unroll
                for (int nt = 0; nt < 4; nt++)
                    MMA_TF32(c[mt][nt], a[mt], b[nt]);
        }
    }

#pragma unroll
    for (int mt = 0; mt < 2; mt++) {
#pragma unroll
        for (int nt = 0; nt < 4; nt++) {
            int row = bm + wm + mt * 16 + lq;
            int col = bn + wn + nt * 8 + lr * 2;
            float b0 = bias[col], b1 = bias[col + 1];
            float v0 = c[mt][nt][0] + b0;
            float v1 = c[mt][nt][1] + b1;
            float v2 = c[mt][nt][2] + b0;
            float v3 = c[mt][nt][3] + b1;
            if (relu) {
                v0 = fmaxf(v0, 0.f); v1 = fmaxf(v1, 0.f);
                v2 = fmaxf(v2, 0.f); v3 = fmaxf(v3, 0.f);
            }
            if (rndout) {
                v0 = tf32f(v0); v1 = tf32f(v1); v2 = tf32f(v2); v3 = tf32f(v3);
            }
            *(float2*)&C[(size_t)row * N + col]       = make_float2(v0, v1);
            *(float2*)&C[(size_t)(row + 8) * N + col] = make_float2(v2, v3);
        }
    }
}

// ---------------- per-head projection GEMM: [4800,256]@[256,32] x 8 heads ----------
// A = g_me [h][4800][256] (tf32-rounded), W = vpw (rounded) cols h*32..h*32+31.
__global__ __launch_bounds__(128) void gemm_proj(
    const float* __restrict__ A, const float* __restrict__ W,
    const float* __restrict__ bias, float* __restrict__ C)
{
    __shared__ float As[3][64][APITCH];
    __shared__ float Bs[3][TBK][36];

    const int h  = blockIdx.x;       // 0..7
    const int bm = blockIdx.y * 64;
    const int t  = threadIdx.x;      // 0..127
    const int lane = t & 31;
    const int warp = t >> 5;
    const int wm = warp * 16;
    const int lq = lane >> 2;
    const int lr = lane & 3;

    const int a_row = t >> 1;          // 0..63
    const int a_col = (t & 1) * 8;     // 0 or 8
    const int b_row = t >> 3;          // 0..15
    const int b_col = (t & 7) * 4;     // 0..28

    const float* Aptr = A + ((size_t)h * BQ + bm + a_row) * Dn + a_col;
    const float* Wptr = W + (size_t)b_row * Dn + h * 32 + b_col;

    float c[4][4];
#pragma unroll
    for (int j = 0; j < 4; j++)
#pragma unroll
        for (int l = 0; l < 4; l++) c[j][l] = 0.f;

    const int nk = Dn / TBK;  // 16

#pragma unroll
    for (int s = 0; s < 2; s++) {
        int kt = s * TBK;
        cp16(&As[s][a_row][a_col],     Aptr + kt);
        cp16(&As[s][a_row][a_col + 4], Aptr + kt + 4);
        cp16(&Bs[s][b_row][b_col],     Wptr + (size_t)kt * Dn);
        asm volatile("cp.async.commit_group;" ::: "memory");
    }

    for (int it = 0; it < nk; it++) {
        asm volatile("cp.async.wait_group 1;" ::: "memory");
        __syncthreads();

        int nxt = it + 2;
        if (nxt < nk) {
            int s = nxt % 3;
            int kt = nxt * TBK;
            cp16(&As[s][a_row][a_col],     Aptr + kt);
            cp16(&As[s][a_row][a_col + 4], Aptr + kt + 4);
            cp16(&Bs[s][b_row][b_col],     Wptr + (size_t)kt * Dn);
        }
        asm volatile("cp.async.commit_group;" ::: "memory");

        const int buf = it % 3;
#pragma unroll
        for (int ks = 0; ks < TBK; ks += 8) {
            uint32_t a[4], b[4][2];
            int mr = wm + lq;
            a[0] = __float_as_uint(As[buf][mr    ][ks + lr]);
            a[1] = __float_as_uint(As[buf][mr + 8][ks + lr]);
            a[2] = __float_as_uint(As[buf][mr    ][ks + lr + 4]);
            a[3] = __float_as_uint(As[buf][mr + 8][ks + lr + 4]);
#pragma unroll
            for (int nt = 0; nt < 4; nt++) {
                int nc = nt * 8 + lq;
                b[nt][0] = __float_as_uint(Bs[buf][ks + lr    ][nc]);
                b[nt][1] = __float_as_uint(Bs[buf][ks + lr + 4][nc]);
            }
#pragma unroll
            for (int nt = 0; nt < 4; nt++)
                MMA_TF32(c[nt], a, b[nt]);
        }
    }

#pragma unroll
    for (int nt = 0; nt < 4; nt++) {
        int row = bm + wm + lq;
        int col = h * 32 + nt * 8 + lr * 2;
        float b0 = bias[col], b1 = bias[col + 1];
        *(float2*)&C[(size_t)row * Dn + col] =
            make_float2(tf32f(c[nt][0] + b0), tf32f(c[nt][1] + b1));
        *(float2*)&C[(size_t)(row + 8) * Dn + col] =
            make_float2(tf32f(c[nt][2] + b0), tf32f(c[nt][3] + b1));
    }
}

// ---------------- fp32 FFMA tiled SGEMM (accuracy-critical logits) ----------------
#define BM 64
#define BNf 64
#define BKf 16

__global__ __launch_bounds__(256) void gemm_f32_kernel(
    const float* __restrict__ A, const float* __restrict__ W,
    const float* __restrict__ bias, float* __restrict__ C,
    int M, int N, int K)
{
    __shared__ float As[BKf][BM];
    __shared__ float Bs[BKf][BNf];
    int tid = threadIdx.x;
    int tx = tid & 15, ty = tid >> 4;
    int bm = blockIdx.y * BM, bn = blockIdx.x * BNf;

    float acc[4][4];
#pragma unroll
    for (int i = 0; i < 4; i++)
#pragma unroll
        for (int j = 0; j < 4; j++) acc[i][j] = 0.f;

    int a_row = tid >> 2;
    int a_col = (tid & 3) * 4;
    int b_row = tid >> 4;
    int b_col = (tid & 15) * 4;

    const float* Aptr = A + (size_t)(bm + a_row) * K + a_col;
    const float* Wptr = W + (size_t)b_row * N + bn + b_col;

    for (int kt = 0; kt < K; kt += BKf) {
        float4 av = *(const float4*)(Aptr + kt);
        As[a_col + 0][a_row] = av.x;
        As[a_col + 1][a_row] = av.y;
        As[a_col + 2][a_row] = av.z;
        As[a_col + 3][a_row] = av.w;
        float4 bv = *(const float4*)(Wptr + (size_t)kt * N);
        *(float4*)&Bs[b_row][b_col] = bv;
        __syncthreads();
#pragma unroll
        for (int kk = 0; kk < BKf; kk++) {
            float ar[4], br[4];
#pragma unroll
            for (int i = 0; i < 4; i++) ar[i] = As[kk][ty + 16 * i];
#pragma unroll
            for (int j = 0; j < 4; j++) br[j] = Bs[kk][tx + 16 * j];
#pragma unroll
            for (int i = 0; i < 4; i++)
#pragma unroll
                for (int j = 0; j < 4; j++) acc[i][j] += ar[i] * br[j];
        }
        __syncthreads();
    }

#pragma unroll
    for (int i = 0; i < 4; i++) {
        int row = bm + ty + 16 * i;
#pragma unroll
        for (int j = 0; j < 4; j++) {
            int col = bn + tx + 16 * j;
            C[(size_t)row * N + col] = acc[i][j] + bias[col];
        }
    }
}

// ---------------- concat ref/off/attw weights into padded [256,128] ----------------
__global__ void concat_w_kernel(
    const float* __restrict__ ref_w, const float* __restrict__ ref_b,
    const float* __restrict__ off_w, const float* __restrict__ off_b,
    const float* __restrict__ attw_w, const float* __restrict__ attw_b,
    float* __restrict__ Wc, float* __restrict__ bc)
{
    int i = blockIdx.x * 256 + threadIdx.x;
    if (i < Dn * 128) {
        int d = i >> 7, j = i & 127;
        float v = 0.f;
        if (j < 2) v = ref_w[d * 2 + j];
        else if (j < 66) v = off_w[d * 64 + (j - 2)];
        else if (j < 98) v = attw_w[d * 32 + (j - 66)];
        Wc[i] = v;
    }
    if (i < 128) {
        float v = 0.f;
        if (i < 2) v = ref_b[i];
        else if (i < 66) v = off_b[i - 2];
        else if (i < 98) v = attw_b[i - 66];
        bc[i] = v;
    }
}

// ---------------- flash self-attention: no-max softmax + packed f32x2 ----------------
#define KT 60

__global__ __launch_bounds__(128) void flash_kernel(
    const float* __restrict__ qkv, float* __restrict__ sa)
{
    __shared__ float4 Ks[KT][8];
    __shared__ float4 Vs[KT][8];

    const int bh = blockIdx.y;
    const int b = bh >> 3, h = bh & 7;
    const int qi = blockIdx.x * 128 + threadIdx.x;
    const bool act = qi < Qn;
    const int tid = threadIdx.x;

    ull q2[16], acc2[16];
    const float* qp = qkv + (size_t)(b * Qn + (act ? qi : 0)) * (3 * Dn) + h * DHn;
#pragma unroll
    for (int i = 0; i < 8; i++) {
        F4U t; t.f = *(const float4*)(qp + i * 4);
        q2[2 * i] = t.u[0]; q2[2 * i + 1] = t.u[1];
    }
#pragma unroll
    for (int i = 0; i < 16; i++) acc2[i] = 0ull;

    float su = 0.f;
    const float scale = 0.17677669529663689f;

    const float* kbase = qkv + (size_t)(b * Qn) * (3 * Dn) + Dn + h * DHn;
    const float* vbase = kbase + Dn;

    for (int t0 = 0; t0 < Qn; t0 += KT) {
        for (int i = tid; i < KT * 8; i += 128) {
            int j = i >> 3, dc = i & 7;
            size_t off = (size_t)(t0 + j) * (3 * Dn) + dc * 4;
            Ks[j][dc] = *(const float4*)(kbase + off);
            Vs[j][dc] = *(const float4*)(vbase + off);
        }
        __syncthreads();

#pragma unroll 2
        for (int j = 0; j < KT; j++) {
            ull s2a = 0ull, s2b = 0ull;
#pragma unroll
            for (int i = 0; i < 4; i++) {
                F4U ka; ka.f = Ks[j][2 * i];
                F4U kb; kb.f = Ks[j][2 * i + 1];
                s2a = fma2(q2[4 * i    ], ka.u[0], s2a);
                s2b = fma2(q2[4 * i + 1], ka.u[1], s2b);
                s2a = fma2(q2[4 * i + 2], kb.u[0], s2a);
                s2b = fma2(q2[4 * i + 3], kb.u[1], s2b);
            }
            F2U ua; ua.u = s2a;
            F2U ub; ub.u = s2b;
            float s = (ua.f.x + ua.f.y + ub.f.x + ub.f.y) * scale;
            float p = __expf(s);
            su += p;
            F2U pp; pp.f = make_float2(p, p);
            ull p2 = pp.u;
#pragma unroll
            for (int i = 0; i < 4; i++) {
                F4U va; va.f = Vs[j][2 * i];
                F4U vb; vb.f = Vs[j][2 * i + 1];
                acc2[4 * i    ] = fma2(p2, va.u[0], acc2[4 * i    ]);
                acc2[4 * i + 1] = fma2(p2, va.u[1], acc2[4 * i + 1]);
                acc2[4 * i + 2] = fma2(p2, vb.u[0], acc2[4 * i + 2]);
                acc2[4 * i + 3] = fma2(p2, vb.u[1], acc2[4 * i + 3]);
            }
        }
        __syncthreads();
    }

    if (act) {
        float inv = 1.f / su;
        float* op = sa + (size_t)(b * Qn + qi) * Dn + h * DHn;
#pragma unroll
        for (int i = 0; i < 8; i++) {
            F2U lo; lo.u = acc2[2 * i];
            F2U hi; hi.u = acc2[2 * i + 1];
            float4 v = make_float4(tf32f(lo.f.x * inv), tf32f(lo.f.y * inv),
                                   tf32f(hi.f.x * inv), tf32f(hi.f.y * inv));
            *(float4*)(op + i * 4) = v;
        }
    }
}

// ---------------- fused residual-add + LayerNorm ----------------
__global__ void add_ln_kernel(const float* __restrict__ a, const float* __restrict__ r,
                              const float* __restrict__ g, const float* __restrict__ be,
                              float* __restrict__ out, float* __restrict__ out_r)
{
    int row = blockIdx.x, t = threadIdx.x;
    size_t idx = (size_t)row * Dn + t;
    float v = a[idx] + r[idx];
    __shared__ float red[8];
    float s = v;
#pragma unroll
    for (int o = 16; o; o >>= 1) s += __shfl_xor_sync(~0u, s, o);
    if ((t & 31) == 0) red[t >> 5] = s;
    __syncthreads();
    float mean = 0.f;
#pragma unroll
    for (int i = 0; i < 8; i++) mean += red[i];
    mean *= (1.f / Dn);
    float d = v - mean;
    float s2 = d * d;
#pragma unroll
    for (int o = 16; o; o >>= 1) s2 += __shfl_xor_sync(~0u, s2, o);
    __syncthreads();
    if ((t & 31) == 0) red[t >> 5] = s2;
    __syncthreads();
    float var = 0.f;
#pragma unroll
    for (int i = 0; i < 8; i++) var += red[i];
    var *= (1.f / Dn);
    float o2 = d * rsqrtf(var + LN_EPS) * g[t] + be[t];
    out[idx] = o2;
    if (out_r) out_r[idx] = tf32f(o2);
}

// ---------------- sampler2: weights + bilinear gather of RAW memory -> m_eff ------
__global__ __launch_bounds__(256) void sampler2_kernel(
    const float* __restrict__ lgbuf, const float* __restrict__ memory,
    float* __restrict__ me)
{
    __shared__ float lg[128];
    __shared__ float sref[2];
    __shared__ float swts[Hn * Pn];
    __shared__ int   srow[128];
    __shared__ float swt[128];

    int bq = blockIdx.x;
    int b = bq / Qn;
    int t = threadIdx.x;

    if (t < 128) lg[t] = lgbuf[(size_t)bq * 128 + t];
    __syncthreads();

    if (t < 2) sref[t] = 1.f / (1.f + expf(-lg[t]));
    else if (t >= 32 && t < 40) {
        int h = t - 32;
        const float* al = &lg[66 + h * 4];
        float m = fmaxf(fmaxf(al[0], al[1]), fmaxf(al[2], al[3]));
        float e0 = expf(al[0]-m), e1 = expf(al[1]-m), e2 = expf(al[2]-m), e3 = expf(al[3]-m);
        float inv = 1.f / (e0 + e1 + e2 + e3);
        swts[h*4+0] = e0*inv; swts[h*4+1] = e1*inv; swts[h*4+2] = e2*inv; swts[h*4+3] = e3*inv;
    }
    __syncthreads();

    if (t < 32) {
        int h = t >> 2, p = t & 3;
        float lx = fminf(fmaxf(sref[0] + lg[2 + h * 8 + p * 2 + 0], 0.f), 1.f);
        float ly = fminf(fmaxf(sref[1] + lg[2 + h * 8 + p * 2 + 1], 0.f), 1.f);
        float sx = lx * (float)(WGn - 1);
        float sy = ly * (float)(HGn - 1);
        float x0f = floorf(sx), y0f = floorf(sy);
        int x0 = min(max((int)x0f, 0), WGn - 1);
        int y0 = min(max((int)y0f, 0), HGn - 1);
        int x1i = min(x0 + 1, WGn - 1);
        int y1i = min(y0 + 1, HGn - 1);
        float wx1 = sx - x0f, wx0 = 1.f - wx1;
        float wy1 = sy - y0f, wy0 = 1.f - wy1;
        float wp = swts[t];
        int rowb = b * HWn;
        int base = t * 4;
        srow[base + 0] = rowb + y0  * WGn + x0;  swt[base + 0] = wp * wx0 * wy0;
        srow[base + 1] = rowb + y1i * WGn + x0;  swt[base + 1] = wp * wx0 * wy1;
        srow[base + 2] = rowb + y0  * WGn + x1i; swt[base + 2] = wp * wx1 * wy0;
        srow[base + 3] = rowb + y1i * WGn + x1i; swt[base + 3] = wp * wx1 * wy1;
    }
    __syncthreads();

    // gather: thread t = dim d; per head accumulate 16 weighted texel rows
#pragma unroll
    for (int h = 0; h < Hn; h++) {
        float acc = 0.f;
#pragma unroll
        for (int i = 0; i < 16; i++)
            acc += swt[h * 16 + i] * memory[(size_t)srow[h * 16 + i] * Dn + t];
        // tf32-round: feeds tf32 projection GEMM
        me[((size_t)h * BQ + bq) * Dn + t] = tf32f(acc);
    }
}

// ---------------- launch ----------------
extern "C" void kernel_launch(void* const* d_in, const int* in_sizes, int n_in,
                              void* d_out, int out_size)
{
    const float* tgt        = (const float*)d_in[0];
    const float* memory     = (const float*)d_in[1];
    const float* in_proj_w  = (const float*)d_in[2];
    const float* in_proj_b  = (const float*)d_in[3];
    const float* out_proj_w = (const float*)d_in[4];
    const float* out_proj_b = (const float*)d_in[5];
    const float* norm1_g    = (const float*)d_in[6];
    const float* norm1_b    = (const float*)d_in[7];
    const float* ref_w      = (const float*)d_in[8];
    const float* ref_b      = (const float*)d_in[9];
    const float* off_w      = (const float*)d_in[10];
    const float* off_b      = (const float*)d_in[11];
    const float* attw_w     = (const float*)d_in[12];
    const float* attw_b     = (const float*)d_in[13];
    const float* vproj_w    = (const float*)d_in[14];
    const float* vproj_b    = (const float*)d_in[15];
    const float* oproj_w    = (const float*)d_in[16];
    const float* oproj_b    = (const float*)d_in[17];
    const float* norm2_g    = (const float*)d_in[18];
    const float* norm2_b    = (const float*)d_in[19];
    const float* lin1_w     = (const float*)d_in[20];
    const float* lin1_b     = (const float*)d_in[21];
    const float* lin2_w     = (const float*)d_in[22];
    const float* lin2_b     = (const float*)d_in[23];
    const float* norm3_g    = (const float*)d_in[24];
    const float* norm3_b    = (const float*)d_in[25];
    float* out = (float*)d_out;

    float *qkv, *sa, *x1, *x2, *x2r, *tmp, *ca, *me, *ff, *wcat, *bcat, *lgb;
    float *ipw, *opw, *vpw, *oqw, *l1w, *l2w, *tgtr;
    cudaGetSymbolAddress((void**)&qkv,  g_qkv);
    cudaGetSymbolAddress((void**)&sa,   g_sa);
    cudaGetSymbolAddress((void**)&x1,   g_x1);
    cudaGetSymbolAddress((void**)&x2,   g_x2);
    cudaGetSymbolAddress((void**)&x2r,  g_x2r);
    cudaGetSymbolAddress((void**)&tmp,  g_tmp);
    cudaGetSymbolAddress((void**)&ca,   g_ca);
    cudaGetSymbolAddress((void**)&me,   g_me);
    cudaGetSymbolAddress((void**)&ff,   g_ff);
    cudaGetSymbolAddress((void**)&wcat, g_wcat);
    cudaGetSymbolAddress((void**)&bcat, g_bcat);
    cudaGetSymbolAddress((void**)&lgb,  g_lg);
    cudaGetSymbolAddress((void**)&ipw,  g_ipw);
    cudaGetSymbolAddress((void**)&opw,  g_opw);
    cudaGetSymbolAddress((void**)&vpw,  g_vpw);
    cudaGetSymbolAddress((void**)&oqw,  g_oqw);
    cudaGetSymbolAddress((void**)&l1w,  g_l1w);
    cudaGetSymbolAddress((void**)&l2w,  g_l2w);
    cudaGetSymbolAddress((void**)&tgtr, g_tgtr);

    const int smem1 = (3 * 64 * APITCH + 3 * TBK * BPITCH) * 4;  // 41472
    cudaFuncSetAttribute((const void*)gemm_tf32_async, cudaFuncAttributeMaxDynamicSharedMemorySize, smem1);

    // 0. pre-round weights + tgt; concat logits weights (fp32)
    round7_kernel<<<2608, 256>>>(
        (const float4*)in_proj_w, (const float4*)out_proj_w, (const float4*)vproj_w,
        (const float4*)oproj_w, (const float4*)lin1_w, (const float4*)lin2_w,
        (const float4*)tgt,
        (float4*)ipw, (float4*)opw, (float4*)vpw, (float4*)oqw,
        (float4*)l1w, (float4*)l2w, (float4*)tgtr);
    concat_w_kernel<<<128, 256>>>(ref_w, ref_b, off_w, off_b, attw_w, attw_b, wcat, bcat);
    // 1. qkv projection [4800,256]@[256,768]
    gemm_tf32_async<<<dim3(768 / TBN, BQ / 64), 256, smem1>>>(tgtr, ipw, in_proj_b, qkv, BQ, 768, Dn, 0, 0);
    // 2. fused self-attention
    flash_kernel<<<dim3((Qn + 127) / 128, Bn * Hn), 128>>>(qkv, sa);
    // 3. out_proj
    gemm_tf32_async<<<dim3(Dn / TBN, BQ / 64), 256, smem1>>>(sa, opw, out_proj_b, tmp, BQ, Dn, Dn, 0, 0);
    // 4. x1 = LN(tgt + sa_out)
    add_ln_kernel<<<BQ, Dn>>>(tgt, tmp, norm1_g, norm1_b, x1, nullptr);
    // 5. logits — fp32 (accuracy-critical)
    gemm_f32_kernel<<<dim3(128 / BNf, BQ / BM), 256>>>(x1, wcat, bcat, lgb, BQ, 128, Dn);
    // 6. sampler2: gather raw memory into per-head effective vectors (NO vproj GEMM!)
    sampler2_kernel<<<BQ, 256>>>(lgb, memory, me);
    // 7. per-head projection: ca = m_eff @ vproj_w (+bias), 0.63 GFLOP
    gemm_proj<<<dim3(Hn, BQ / 64), 128>>>(me, vpw, vproj_b, ca);
    // 8. oproj
    gemm_tf32_async<<<dim3(Dn / TBN, BQ / 64), 256, smem1>>>(ca, oqw, oproj_b, tmp, BQ, Dn, Dn, 0, 0);
    // 9. x2 = LN(x1 + ca_out); x2r = tf32(x2)
    add_ln_kernel<<<BQ, Dn>>>(x1, tmp, norm2_g, norm2_b, x2, x2r);
    // 10. FFN lin1 + ReLU (tf32-rounded out)
    gemm_tf32_async<<<dim3(Fn / TBN, BQ / 64), 256, smem1>>>(x2r, l1w, lin1_b, ff, BQ, Fn, Dn, 1, 1);
    // 11. FFN lin2
    gemm_tf32_async<<<dim3(Dn / TBN, BQ / 64), 256, smem1>>>(ff, l2w, lin2_b, tmp, BQ, Dn, Fn, 0, 0);
    // 12. out = LN(x2 + ffn)
    add_ln_kernel<<<BQ, Dn>>>(x2, tmp, norm3_g, norm3_b, out, nullptr);
}

// round 10
// speedup vs baseline: 1.3505x; 1.0061x over previous
#include <cuda_runtime.h>
#include <math.h>
#include <stdint.h>

#define Bn 16
#define Qn 300
#define Dn 256
#define Hn 8
#define Pn 4
#define Fn 2048
#define HGn 100
#define WGn 100
#define HWn 10000
#define DHn 32
#define LN_EPS 1e-5f

#define BQ (Bn*Qn)            // 4800
#define MEMROWS (Bn*HWn)      // 160000

typedef unsigned long long ull;

// ---------------- scratch (allocation-free: __device__ globals) ----------------
__device__ float g_qkv[BQ*3*Dn];
__device__ float g_sa[BQ*Dn];
__device__ float g_x1[BQ*Dn];
__device__ float g_x2[BQ*Dn];
__device__ float g_x2r[BQ*Dn];
__device__ float g_tmp[BQ*Dn];
__device__ float g_ca[BQ*Dn];
__device__ float g_me[Hn*BQ*Dn];      // per-head effective memory vectors [h][bq][d]
__device__ float g_ff[BQ*Fn];
__device__ float g_wcat[Dn*128];
__device__ float g_bcat[128];
__device__ float g_lg[BQ*128];
// tf32-pre-rounded copies
__device__ float g_ipw[Dn*768];
__device__ float g_opw[Dn*Dn];
__device__ float g_vpw[Dn*Dn];
__device__ float g_oqw[Dn*Dn];
__device__ float g_l1w[Dn*Fn];
__device__ float g_l2w[Fn*Dn];
__device__ float g_tgtr[BQ*Dn];

__device__ __forceinline__ uint32_t tf32r(float x) {
    float y;
    asm("cvt.rna.tf32.f32 %0, %1;" : "=f"(y) : "f"(x));
    return __float_as_uint(y);
}
__device__ __forceinline__ float tf32f(float x) { return __uint_as_float(tf32r(x)); }

__device__ __forceinline__ ull fma2(ull a, ull b, ull c) {
    ull d;
    asm("fma.rn.f32x2 %0, %1, %2, %3;" : "=l"(d) : "l"(a), "l"(b), "l"(c));
    return d;
}

union F4U { float4 f; ull u[2]; };
union F2U { float2 f; ull u; };

// ---------------- one-shot tf32 rounding of weights + tgt ----------------
__global__ void round7_kernel(
    const float4* __restrict__ ipw, const float4* __restrict__ opw,
    const float4* __restrict__ vpw, const float4* __restrict__ oqw,
    const float4* __restrict__ l1w, const float4* __restrict__ l2w,
    const float4* __restrict__ tgt,
    float4* d_ipw, float4* d_opw, float4* d_vpw, float4* d_oqw,
    float4* d_l1w, float4* d_l2w, float4* d_tgt)
{
    int bi = blockIdx.x;
    const float4* s; float4* d; int base;
    if      (bi <  192) { s = ipw; d = d_ipw; base = bi; }
    else if (bi <  256) { s = opw; d = d_opw; base = bi - 192; }
    else if (bi <  320) { s = vpw; d = d_vpw; base = bi - 256; }
    else if (bi <  384) { s = oqw; d = d_oqw; base = bi - 320; }
    else if (bi <  896) { s = l1w; d = d_l1w; base = bi - 384; }
    else if (bi < 1408) { s = l2w; d = d_l2w; base = bi - 896; }
    else                { s = tgt; d = d_tgt; base = bi - 1408; }
    int idx = base * 256 + threadIdx.x;
    float4 v = s[idx];
    v.x = tf32f(v.x); v.y = tf32f(v.y); v.z = tf32f(v.z); v.w = tf32f(v.w);
    d[idx] = v;
}

// ---------------- common GEMM constants ----------------
#define TBN 128
#define TBK 16
#define APITCH (TBK + 4)    // 20
#define BPITCH (TBN + 8)    // 136

__device__ __forceinline__ void cp16(void* dst, const void* src) {
    uint32_t d = (uint32_t)__cvta_generic_to_shared(dst);
    asm volatile("cp.async.ca.shared.global [%0], [%1], 16;" :: "r"(d), "l"(src));
}

#define MMA_TF32(c, a, b) \
    asm volatile( \
        "mma.sync.aligned.m16n8k8.row.col.f32.tf32.tf32.f32 " \
        "{%0,%1,%2,%3}, {%4,%5,%6,%7}, {%8,%9}, {%0,%1,%2,%3};" \
        : "+f"((c)[0]), "+f"((c)[1]), "+f"((c)[2]), "+f"((c)[3]) \
        : "r"((a)[0]), "r"((a)[1]), "r"((a)[2]), "r"((a)[3]), \
          "r"((b)[0]), "r"((b)[1]))

// ---------------- generic 64x128 tf32 GEMM (pre-rounded A and B) ----------------
__global__ __launch_bounds__(256) void gemm_tf32_async(
    const float* __restrict__ A, const float* __restrict__ W,
    const float* __restrict__ bias, float* __restrict__ C,
    int M, int N, int K, int relu, int rndout)
{
    extern __shared__ float smem[];
    float (*As)[64][APITCH] = (float(*)[64][APITCH])smem;
    float (*Bs)[TBK][BPITCH] = (float(*)[TBK][BPITCH])(smem + 3 * 64 * APITCH);

    const int tid  = threadIdx.x;
    const int lane = tid & 31;
    const int warp = tid >> 5;
    const int wm = (warp >> 2) * 32;
    const int wn = (warp & 3) * 32;
    const int bm = blockIdx.y * 64;
    const int bn = blockIdx.x * TBN;

    const int lq = lane >> 2;
    const int lr = lane & 3;

    const int a_row = tid >> 2;
    const int a_col = (tid & 3) * 4;
    const int b_row = tid >> 4;
    const int b_col = (tid & 15) * 8;

    const float* Aptr = A + (size_t)(bm + a_row) * K + a_col;
    const float* Wptr = W + (size_t)b_row * N + bn + b_col;

    float c[2][4][4];
#pragma unroll
    for (int i = 0; i < 2; i++)
#pragma unroll
        for (int j = 0; j < 4; j++)
#pragma unroll
            for (int l = 0; l < 4; l++) c[i][j][l] = 0.f;

    const int nk = K / TBK;

#pragma unroll
    for (int s = 0; s < 2; s++) {
        int kt = s * TBK;
        cp16(&As[s][a_row][a_col], Aptr + kt);
        cp16(&Bs[s][b_row][b_col],     Wptr + (size_t)kt * N);
        cp16(&Bs[s][b_row][b_col + 4], Wptr + (size_t)kt * N + 4);
        asm volatile("cp.async.commit_group;" ::: "memory");
    }

    for (int it = 0; it < nk; it++) {
        asm volatile("cp.async.wait_group 1;" ::: "memory");
        __syncthreads();

        int nxt = it + 2;
        if (nxt < nk) {
            int s = nxt % 3;
            int kt = nxt * TBK;
            cp16(&As[s][a_row][a_col], Aptr + kt);
            cp16(&Bs[s][b_row][b_col],     Wptr + (size_t)kt * N);
            cp16(&Bs[s][b_row][b_col + 4], Wptr + (size_t)kt * N + 4);
        }
        asm volatile("cp.async.commit_group;" ::: "memory");

        const int buf = it % 3;
#pragma unroll
        for (int ks = 0; ks < TBK; ks += 8) {
            uint32_t a[2][4], b[4][2];
#pragma unroll
            for (int mt = 0; mt < 2; mt++) {
                int mr = wm + mt * 16 + lq;
                a[mt][0] = __float_as_uint(As[buf][mr    ][ks + lr]);
                a[mt][1] = __float_as_uint(As[buf][mr + 8][ks + lr]);
                a[mt][2] = __float_as_uint(As[buf][mr    ][ks + lr + 4]);
                a[mt][3] = __float_as_uint(As[buf][mr + 8][ks + lr + 4]);
            }
#pragma unroll
            for (int nt = 0; nt < 4; nt++) {
                int nc = wn + nt * 8 + lq;
                b[nt][0] = __float_as_uint(Bs[buf][ks + lr    ][nc]);
                b[nt][1] = __float_as_uint(Bs[buf][ks + lr + 4][nc]);
            }
#pragma unroll
            for (int mt = 0; mt < 2; mt++)
#pragma unroll
                for (int nt = 0; nt < 4; nt++)
                    MMA_TF32(c[mt][nt], a[mt], b[nt]);
        }
    }

#pragma unroll
    for (int mt = 0; mt < 2; mt++) {
#pragma unroll
        for (int nt = 0; nt < 4; nt++) {
            int row = bm + wm + mt * 16 + lq;
            int col = bn + wn + nt * 8 + lr * 2;
            float b0 = bias[col], b1 = bias[col + 1];
            float v0 = c[mt][nt][0] + b0;
            float v1 = c[mt][nt][1] + b1;
            float v2 = c[mt][nt][2] + b0;
            float v3 = c[mt][nt][3] + b1;
            if (relu) {
                v0 = fmaxf(v0, 0.f); v1 = fmaxf(v1, 0.f);
                v2 = fmaxf(v2, 0.f); v3 = fmaxf(v3, 0.f);
            }
            if (rndout) {
                v0 = tf32f(v0); v1 = tf32f(v1); v2 = tf32f(v2); v3 = tf32f(v3);
            }
            *(float2*)&C[(size_t)row * N + col]       = make_float2(v0, v1);
            *(float2*)&C[(size_t)(row + 8) * N + col] = make_float2(v2, v3);
        }
    }
}

// ---------------- per-head projection GEMM: [4800,256]@[256,32] x 8 heads ----------
__global__ __launch_bounds__(128) void gemm_proj(
    const float* __restrict__ A, const float* __restrict__ W,
    const float* __restrict__ bias, float* __restrict__ C)
{
    __shared__ float As[3][64][APITCH];
    __shared__ float Bs[3][TBK][36];

    const int h  = blockIdx.x;       // 0..7
    const int bm = blockIdx.y * 64;
    const int t  = threadIdx.x;      // 0..127
    const int lane = t & 31;
    const int warp = t >> 5;
    const int wm = warp * 16;
    const int lq = lane >> 2;
    const int lr = lane & 3;

    const int a_row = t >> 1;          // 0..63
    const int a_col = (t & 1) * 8;     // 0 or 8
    const int b_row = t >> 3;          // 0..15
    const int b_col = (t & 7) * 4;     // 0..28

    const float* Aptr = A + ((size_t)h * BQ + bm + a_row) * Dn + a_col;
    const float* Wptr = W + (size_t)b_row * Dn + h * 32 + b_col;

    float c[4][4];
#pragma unroll
    for (int j = 0; j < 4; j++)
#pragma unroll
        for (int l = 0; l < 4; l++) c[j][l] = 0.f;

    const int nk = Dn / TBK;  // 16

#pragma unroll
    for (int s = 0; s < 2; s++) {
        int kt = s * TBK;
        cp16(&As[s][a_row][a_col],     Aptr + kt);
        cp16(&As[s][a_row][a_col + 4], Aptr + kt + 4);
        cp16(&Bs[s][b_row][b_col],     Wptr + (size_t)kt * Dn);
        asm volatile("cp.async.commit_group;" ::: "memory");
    }

    for (int it = 0; it < nk; it++) {
        asm volatile("cp.async.wait_group 1;" ::: "memory");
        __syncthreads();

        int nxt = it + 2;
        if (nxt < nk) {
            int s = nxt % 3;
            int kt = nxt * TBK;
            cp16(&As[s][a_row][a_col],     Aptr + kt);
            cp16(&As[s][a_row][a_col + 4], Aptr + kt + 4);
            cp16(&Bs[s][b_row][b_col],     Wptr + (size_t)kt * Dn);
        }
        asm volatile("cp.async.commit_group;" ::: "memory");

        const int buf = it % 3;
#pragma unroll
        for (int ks = 0; ks < TBK; ks += 8) {
            uint32_t a[4], b[4][2];
            int mr = wm + lq;
            a[0] = __float_as_uint(As[buf][mr    ][ks + lr]);
            a[1] = __float_as_uint(As[buf][mr + 8][ks + lr]);
            a[2] = __float_as_uint(As[buf][mr    ][ks + lr + 4]);
            a[3] = __float_as_uint(As[buf][mr + 8][ks + lr + 4]);
#pragma unroll
            for (int nt = 0; nt < 4; nt++) {
                int nc = nt * 8 + lq;
                b[nt][0] = __float_as_uint(Bs[buf][ks + lr    ][nc]);
                b[nt][1] = __float_as_uint(Bs[buf][ks + lr + 4][nc]);
            }
#pragma unroll
            for (int nt = 0; nt < 4; nt++)
                MMA_TF32(c[nt], a, b[nt]);
        }
    }

#pragma unroll
    for (int nt = 0; nt < 4; nt++) {
        int row = bm + wm + lq;
        int col = h * 32 + nt * 8 + lr * 2;
        float b0 = bias[col], b1 = bias[col + 1];
        *(float2*)&C[(size_t)row * Dn + col] =
            make_float2(tf32f(c[nt][0] + b0), tf32f(c[nt][1] + b1));
        *(float2*)&C[(size_t)(row + 8) * Dn + col] =
            make_float2(tf32f(c[nt][2] + b0), tf32f(c[nt][3] + b1));
    }
}

// ---------------- fp32 FFMA tiled SGEMM (accuracy-critical logits) ----------------
#define BM 64
#define BNf 64
#define BKf 16

__global__ __launch_bounds__(256) void gemm_f32_kernel(
    const float* __restrict__ A, const float* __restrict__ W,
    const float* __restrict__ bias, float* __restrict__ C,
    int M, int N, int K)
{
    __shared__ float As[BKf][BM];
    __shared__ float Bs[BKf][BNf];
    int tid = threadIdx.x;
    int tx = tid & 15, ty = tid >> 4;
    int bm = blockIdx.y * BM, bn = blockIdx.x * BNf;

    float acc[4][4];
#pragma unroll
    for (int i = 0; i < 4; i++)
#pragma unroll
        for (int j = 0; j < 4; j++) acc[i][j] = 0.f;

    int a_row = tid >> 2;
    int a_col = (tid & 3) * 4;
    int b_row = tid >> 4;
    int b_col = (tid & 15) * 4;

    const float* Aptr = A + (size_t)(bm + a_row) * K + a_col;
    const float* Wptr = W + (size_t)b_row * N + bn + b_col;

    for (int kt = 0; kt < K; kt += BKf) {
        float4 av = *(const float4*)(Aptr + kt);
        As[a_col + 0][a_row] = av.x;
        As[a_col + 1][a_row] = av.y;
        As[a_col + 2][a_row] = av.z;
        As[a_col + 3][a_row] = av.w;
        float4 bv = *(const float4*)(Wptr + (size_t)kt * N);
        *(float4*)&Bs[b_row][b_col] = bv;
        __syncthreads();
#pragma unroll
        for (int kk = 0; kk < BKf; kk++) {
            float ar[4], br[4];
#pragma unroll
            for (int i = 0; i < 4; i++) ar[i] = As[kk][ty + 16 * i];
#pragma unroll
            for (int j = 0; j < 4; j++) br[j] = Bs[kk][tx + 16 * j];
#pragma unroll
            for (int i = 0; i < 4; i++)
#pragma unroll
                for (int j = 0; j < 4; j++) acc[i][j] += ar[i] * br[j];
        }
        __syncthreads();
    }

#pragma unroll
    for (int i = 0; i < 4; i++) {
        int row = bm + ty + 16 * i;
#pragma unroll
        for (int j = 0; j < 4; j++) {
            int col = bn + tx + 16 * j;
            C[(size_t)row * N + col] = acc[i][j] + bias[col];
        }
    }
}

// ---------------- concat ref/off/attw weights into padded [256,128] ----------------
__global__ void concat_w_kernel(
    const float* __restrict__ ref_w, const float* __restrict__ ref_b,
    const float* __restrict__ off_w, const float* __restrict__ off_b,
    const float* __restrict__ attw_w, const float* __restrict__ attw_b,
    float* __restrict__ Wc, float* __restrict__ bc)
{
    int i = blockIdx.x * 256 + threadIdx.x;
    if (i < Dn * 128) {
        int d = i >> 7, j = i & 127;
        float v = 0.f;
        if (j < 2) v = ref_w[d * 2 + j];
        else if (j < 66) v = off_w[d * 64 + (j - 2)];
        else if (j < 98) v = attw_w[d * 32 + (j - 66)];
        Wc[i] = v;
    }
    if (i < 128) {
        float v = 0.f;
        if (i < 2) v = ref_b[i];
        else if (i < 66) v = off_b[i - 2];
        else if (i < 98) v = attw_b[i - 66];
        bc[i] = v;
    }
}

// ---------------- flash self-attention: 2 queries/thread, shared K/V smem reads ----
// One block per (b,h): 160 threads; thread t handles queries t and t+160.
#define KT 60

__global__ __launch_bounds__(160) void flash_kernel(
    const float* __restrict__ qkv, float* __restrict__ sa)
{
    __shared__ float4 Ks[KT][8];
    __shared__ float4 Vs[KT][8];

    const int bh = blockIdx.x;
    const int b = bh >> 3, h = bh & 7;
    const int tid = threadIdx.x;
    const int qi0 = tid;             // 0..159, always < 300
    const int qi1 = tid + 160;       // 160..319
    const bool act1 = qi1 < Qn;      // tid < 140

    ull q0[16], q1[16], a0[16], a1[16];
    const float* qp0 = qkv + (size_t)(b * Qn + qi0) * (3 * Dn) + h * DHn;
    const float* qp1 = qkv + (size_t)(b * Qn + (act1 ? qi1 : 0)) * (3 * Dn) + h * DHn;
#pragma unroll
    for (int i = 0; i < 8; i++) {
        F4U t0; t0.f = *(const float4*)(qp0 + i * 4);
        q0[2 * i] = t0.u[0]; q0[2 * i + 1] = t0.u[1];
        F4U t1; t1.f = *(const float4*)(qp1 + i * 4);
        q1[2 * i] = t1.u[0]; q1[2 * i + 1] = t1.u[1];
    }
#pragma unroll
    for (int i = 0; i < 16; i++) { a0[i] = 0ull; a1[i] = 0ull; }

    float su0 = 0.f, su1 = 0.f;
    const float scale = 0.17677669529663689f;  // 1/sqrt(32)

    const float* kbase = qkv + (size_t)(b * Qn) * (3 * Dn) + Dn + h * DHn;
    const float* vbase = kbase + Dn;

    for (int t0 = 0; t0 < Qn; t0 += KT) {
        // cooperative tile load: 480 float4 per array, 160 threads -> 3 each
        for (int i = tid; i < KT * 8; i += 160) {
            int j = i >> 3, dc = i & 7;
            size_t off = (size_t)(t0 + j) * (3 * Dn) + dc * 4;
            Ks[j][dc] = *(const float4*)(kbase + off);
            Vs[j][dc] = *(const float4*)(vbase + off);
        }
        __syncthreads();

#pragma unroll 2
        for (int j = 0; j < KT; j++) {
            ull k2[8];
#pragma unroll
            for (int i = 0; i < 4; i++) {
                F4U kk; kk.f = Ks[j][i * 2];
                k2[2 * i] = kk.u[0];
                F4U kk2; kk2.f = Ks[j][i * 2 + 1];
                k2[2 * i + 1] = kk2.u[1];
                // note: need all 4 halves; load properly below
            }
            // reload cleanly: 8 ull = full 32-float K row
            {
                F4U w0; w0.f = Ks[j][0]; F4U w1; w1.f = Ks[j][1];
                F4U w2; w2.f = Ks[j][2]; F4U w3; w3.f = Ks[j][3];
                F4U w4; w4.f = Ks[j][4]; F4U w5; w5.f = Ks[j][5];
                F4U w6; w6.f = Ks[j][6]; F4U w7; w7.f = Ks[j][7];
                k2[0] = w0.u[0]; k2[1] = w0.u[1];
                k2[2] = w1.u[0]; k2[3] = w1.u[1];
                k2[4] = w2.u[0]; k2[5] = w2.u[1];
                k2[6] = w3.u[0]; k2[7] = w3.u[1];
                ull k2b[8];
                k2b[0] = w4.u[0]; k2b[1] = w4.u[1];
                k2b[2] = w5.u[0]; k2b[3] = w5.u[1];
                k2b[4] = w6.u[0]; k2b[5] = w6.u[1];
                k2b[6] = w7.u[0]; k2b[7] = w7.u[1];

                ull s0a = 0ull, s0b = 0ull, s1a = 0ull, s1b = 0ull;
#pragma unroll
                for (int i = 0; i < 8; i++) {
                    ull kv = (i < 8) ? k2[i] : 0ull;
                    s0a = fma2(q0[i], k2[i], s0a);
                    s1a = fma2(q1[i], k2[i], s1a);
                    (void)kv;
                }
#pragma unroll
                for (int i = 0; i < 8; i++) {
                    s0b = fma2(q0[8 + i], k2b[i], s0b);
                    s1b = fma2(q1[8 + i], k2b[i], s1b);
                }
                F2U u0a; u0a.u = s0a; F2U u0b; u0b.u = s0b;
                F2U u1a; u1a.u = s1a; F2U u1b; u1b.u = s1b;
                float s0 = (u0a.f.x + u0a.f.y + u0b.f.x + u0b.f.y) * scale;
                float s1 = (u1a.f.x + u1a.f.y + u1b.f.x + u1b.f.y) * scale;
                float p0 = __expf(s0);
                float p1 = __expf(s1);
                su0 += p0;
                su1 += p1;
                F2U pp0; pp0.f = make_float2(p0, p0);
                F2U pp1; pp1.f = make_float2(p1, p1);
                ull p02 = pp0.u, p12 = pp1.u;

                F4U v0; v0.f = Vs[j][0]; F4U v1; v1.f = Vs[j][1];
                F4U v2; v2.f = Vs[j][2]; F4U v3; v3.f = Vs[j][3];
                F4U v4; v4.f = Vs[j][4]; F4U v5; v5.f = Vs[j][5];
                F4U v6; v6.f = Vs[j][6]; F4U v7; v7.f = Vs[j][7];
                ull vv[16] = { v0.u[0], v0.u[1], v1.u[0], v1.u[1],
                               v2.u[0], v2.u[1], v3.u[0], v3.u[1],
                               v4.u[0], v4.u[1], v5.u[0], v5.u[1],
                               v6.u[0], v6.u[1], v7.u[0], v7.u[1] };
#pragma unroll
                for (int i = 0; i < 16; i++) {
                    a0[i] = fma2(p02, vv[i], a0[i]);
                    a1[i] = fma2(p12, vv[i], a1[i]);
                }
            }
        }
        __syncthreads();
    }

    {
        float inv0 = 1.f / su0;
        float* op0 = sa + (size_t)(b * Qn + qi0) * Dn + h * DHn;
#pragma unroll
        for (int i = 0; i < 8; i++) {
            F2U lo; lo.u = a0[2 * i];
            F2U hi; hi.u = a0[2 * i + 1];
            float4 v = make_float4(tf32f(lo.f.x * inv0), tf32f(lo.f.y * inv0),
                                   tf32f(hi.f.x * inv0), tf32f(hi.f.y * inv0));
            *(float4*)(op0 + i * 4) = v;
        }
    }
    if (act1) {
        float inv1 = 1.f / su1;
        float* op1 = sa + (size_t)(b * Qn + qi1) * Dn + h * DHn;
#pragma unroll
        for (int i = 0; i < 8; i++) {
            F2U lo; lo.u = a1[2 * i];
            F2U hi; hi.u = a1[2 * i + 1];
            float4 v = make_float4(tf32f(lo.f.x * inv1), tf32f(lo.f.y * inv1),
                                   tf32f(hi.f.x * inv1), tf32f(hi.f.y * inv1));
            *(float4*)(op1 + i * 4) = v;
        }
    }
}

// ---------------- fused residual-add + LayerNorm ----------------
__global__ void add_ln_kernel(const float* __restrict__ a, const float* __restrict__ r,
                              const float* __restrict__ g, const float* __restrict__ be,
                              float* __restrict__ out, float* __restrict__ out_r)
{
    int row = blockIdx.x, t = threadIdx.x;
    size_t idx = (size_t)row * Dn + t;
    float v = a[idx] + r[idx];
    __shared__ float red[8];
    float s = v;
#pragma unroll
    for (int o = 16; o; o >>= 1) s += __shfl_xor_sync(~0u, s, o);
    if ((t & 31) == 0) red[t >> 5] = s;
    __syncthreads();
    float mean = 0.f;
#pragma unroll
    for (int i = 0; i < 8; i++) mean += red[i];
    mean *= (1.f / Dn);
    float d = v - mean;
    float s2 = d * d;
#pragma unroll
    for (int o = 16; o; o >>= 1) s2 += __shfl_xor_sync(~0u, s2, o);
    __syncthreads();
    if ((t & 31) == 0) red[t >> 5] = s2;
    __syncthreads();
    float var = 0.f;
#pragma unroll
    for (int i = 0; i < 8; i++) var += red[i];
    var *= (1.f / Dn);
    float o2 = d * rsqrtf(var + LN_EPS) * g[t] + be[t];
    out[idx] = o2;
    if (out_r) out_r[idx] = tf32f(o2);
}

// ---------------- sampler2: weights + bilinear gather of RAW memory -> m_eff ------
__global__ __launch_bounds__(256) void sampler2_kernel(
    const float* __restrict__ lgbuf, const float* __restrict__ memory,
    float* __restrict__ me)
{
    __shared__ float lg[128];
    __shared__ float sref[2];
    __shared__ float swts[Hn * Pn];
    __shared__ int   srow[128];
    __shared__ float swt[128];

    int bq = blockIdx.x;
    int b = bq / Qn;
    int t = threadIdx.x;

    if (t < 128) lg[t] = lgbuf[(size_t)bq * 128 + t];
    __syncthreads();

    if (t < 2) sref[t] = 1.f / (1.f + expf(-lg[t]));
    else if (t >= 32 && t < 40) {
        int h = t - 32;
        const float* al = &lg[66 + h * 4];
        float m = fmaxf(fmaxf(al[0], al[1]), fmaxf(al[2], al[3]));
        float e0 = expf(al[0]-m), e1 = expf(al[1]-m), e2 = expf(al[2]-m), e3 = expf(al[3]-m);
        float inv = 1.f / (e0 + e1 + e2 + e3);
        swts[h*4+0] = e0*inv; swts[h*4+1] = e1*inv; swts[h*4+2] = e2*inv; swts[h*4+3] = e3*inv;
    }
    __syncthreads();

    if (t < 32) {
        int h = t >> 2, p = t & 3;
        float lx = fminf(fmaxf(sref[0] + lg[2 + h * 8 + p * 2 + 0], 0.f), 1.f);
        float ly = fminf(fmaxf(sref[1] + lg[2 + h * 8 + p * 2 + 1], 0.f), 1.f);
        float sx = lx * (float)(WGn - 1);
        float sy = ly * (float)(HGn - 1);
        float x0f = floorf(sx), y0f = floorf(sy);
        int x0 = min(max((int)x0f, 0), WGn - 1);
        int y0 = min(max((int)y0f, 0), HGn - 1);
        int x1i = min(x0 + 1, WGn - 1);
        int y1i = min(y0 + 1, HGn - 1);
        float wx1 = sx - x0f, wx0 = 1.f - wx1;
        float wy1 = sy - y0f, wy0 = 1.f - wy1;
        float wp = swts[t];
        int rowb = b * HWn;
        int base = t * 4;
        srow[base + 0] = rowb + y0  * WGn + x0;  swt[base + 0] = wp * wx0 * wy0;
        srow[base + 1] = rowb + y1i * WGn + x0;  swt[base + 1] = wp * wx0 * wy1;
        srow[base + 2] = rowb + y0  * WGn + x1i; swt[base + 2] = wp * wx1 * wy0;
        srow[base + 3] = rowb + y1i * WGn + x1i; swt[base + 3] = wp * wx1 * wy1;
    }
    __syncthreads();

#pragma unroll
    for (int h = 0; h < Hn; h++) {
        float acc = 0.f;
#pragma unroll
        for (int i = 0; i < 16; i++)
            acc += swt[h * 16 + i] * memory[(size_t)srow[h * 16 + i] * Dn + t];
        me[((size_t)h * BQ + bq) * Dn + t] = tf32f(acc);
    }
}

// ---------------- launch ----------------
extern "C" void kernel_launch(void* const* d_in, const int* in_sizes, int n_in,
                              void* d_out, int out_size)
{
    const float* tgt        = (const float*)d_in[0];
    const float* memory     = (const float*)d_in[1];
    const float* in_proj_w  = (const float*)d_in[2];
    const float* in_proj_b  = (const float*)d_in[3];
    const float* out_proj_w = (const float*)d_in[4];
    const float* out_proj_b = (const float*)d_in[5];
    const float* norm1_g    = (const float*)d_in[6];
    const float* norm1_b    = (const float*)d_in[7];
    const float* ref_w      = (const float*)d_in[8];
    const float* ref_b      = (const float*)d_in[9];
    const float* off_w      = (const float*)d_in[10];
    const float* off_b      = (const float*)d_in[11];
    const float* attw_w     = (const float*)d_in[12];
    const float* attw_b     = (const float*)d_in[13];
    const float* vproj_w    = (const float*)d_in[14];
    const float* vproj_b    = (const float*)d_in[15];
    const float* oproj_w    = (const float*)d_in[16];
    const float* oproj_b    = (const float*)d_in[17];
    const float* norm2_g    = (const float*)d_in[18];
    const float* norm2_b    = (const float*)d_in[19];
    const float* lin1_w     = (const float*)d_in[20];
    const float* lin1_b     = (const float*)d_in[21];
    const float* lin2_w     = (const float*)d_in[22];
    const float* lin2_b     = (const float*)d_in[23];
    const float* norm3_g    = (const float*)d_in[24];
    const float* norm3_b    = (const float*)d_in[25];
    float* out = (float*)d_out;

    float *qkv, *sa, *x1, *x2, *x2r, *tmp, *ca, *me, *ff, *wcat, *bcat, *lgb;
    float *ipw, *opw, *vpw, *oqw, *l1w, *l2w, *tgtr;
    cudaGetSymbolAddress((void**)&qkv,  g_qkv);
    cudaGetSymbolAddress((void**)&sa,   g_sa);
    cudaGetSymbolAddress((void**)&x1,   g_x1);
    cudaGetSymbolAddress((void**)&x2,   g_x2);
    cudaGetSymbolAddress((void**)&x2r,  g_x2r);
    cudaGetSymbolAddress((void**)&tmp,  g_tmp);
    cudaGetSymbolAddress((void**)&ca,   g_ca);
    cudaGetSymbolAddress((void**)&me,   g_me);
    cudaGetSymbolAddress((void**)&ff,   g_ff);
    cudaGetSymbolAddress((void**)&wcat, g_wcat);
    cudaGetSymbolAddress((void**)&bcat, g_bcat);
    cudaGetSymbolAddress((void**)&lgb,  g_lg);
    cudaGetSymbolAddress((void**)&ipw,  g_ipw);
    cudaGetSymbolAddress((void**)&opw,  g_opw);
    cudaGetSymbolAddress((void**)&vpw,  g_vpw);
    cudaGetSymbolAddress((void**)&oqw,  g_oqw);
    cudaGetSymbolAddress((void**)&l1w,  g_l1w);
    cudaGetSymbolAddress((void**)&l2w,  g_l2w);
    cudaGetSymbolAddress((void**)&tgtr, g_tgtr);

    const int smem1 = (3 * 64 * APITCH + 3 * TBK * BPITCH) * 4;  // 41472
    cudaFuncSetAttribute((const void*)gemm_tf32_async, cudaFuncAttributeMaxDynamicSharedMemorySize, smem1);

    // 0. pre-round weights + tgt; concat logits weights (fp32)
    round7_kernel<<<2608, 256>>>(
        (const float4*)in_proj_w, (const float4*)out_proj_w, (const float4*)vproj_w,
        (const float4*)oproj_w, (const float4*)lin1_w, (const float4*)lin2_w,
        (const float4*)tgt,
        (float4*)ipw, (float4*)opw, (float4*)vpw, (float4*)oqw,
        (float4*)l1w, (float4*)l2w, (float4*)tgtr);
    concat_w_kernel<<<128, 256>>>(ref_w, ref_b, off_w, off_b, attw_w, attw_b, wcat, bcat);
    // 1. qkv projection [4800,256]@[256,768]
    gemm_tf32_async<<<dim3(768 / TBN, BQ / 64), 256, smem1>>>(tgtr, ipw, in_proj_b, qkv, BQ, 768, Dn, 0, 0);
    // 2. fused self-attention (2 queries/thread)
    flash_kernel<<<Bn * Hn, 160>>>(qkv, sa);
    // 3. out_proj
    gemm_tf32_async<<<dim3(Dn / TBN, BQ / 64), 256, smem1>>>(sa, opw, out_proj_b, tmp, BQ, Dn, Dn, 0, 0);
    // 4. x1 = LN(tgt + sa_out)
    add_ln_kernel<<<BQ, Dn>>>(tgt, tmp, norm1_g, norm1_b, x1, nullptr);
    // 5. logits — fp32 (accuracy-critical)
    gemm_f32_kernel<<<dim3(128 / BNf, BQ / BM), 256>>>(x1, wcat, bcat, lgb, BQ, 128, Dn);
    // 6. sampler2: gather raw memory into per-head effective vectors
    sampler2_kernel<<<BQ, 256>>>(lgb, memory, me);
    // 7. per-head projection: ca = m_eff @ vproj_w (+bias)
    gemm_proj<<<dim3(Hn, BQ / 64), 128>>>(me, vpw, vproj_b, ca);
    // 8. oproj
    gemm_tf32_async<<<dim3(Dn / TBN, BQ / 64), 256, smem1>>>(ca, oqw, oproj_b, tmp, BQ, Dn, Dn, 0, 0);
    // 9. x2 = LN(x1 + ca_out); x2r = tf32(x2)
    add_ln_kernel<<<BQ, Dn>>>(x1, tmp, norm2_g, norm2_b, x2, x2r);
    // 10. FFN lin1 + ReLU (tf32-rounded out)
    gemm_tf32_async<<<dim3(Fn / TBN, BQ / 64), 256, smem1>>>(x2r, l1w, lin1_b, ff, BQ, Fn, Dn, 1, 1);
    // 11. FFN lin2
    gemm_tf32_async<<<dim3(Dn / TBN, BQ / 64), 256, smem1>>>(ff, l2w, lin2_b, tmp, BQ, Dn, Fn, 0, 0);
    // 12. out = LN(x2 + ffn)
    add_ln_kernel<<<BQ, Dn>>>(x2, tmp, norm3_g, norm3_b, out, nullptr);
}